// round 6
// baseline (speedup 1.0000x reference)
#include <cuda_runtime.h>

#define EPS 1e-3f
#define B    8
#define CIN  4
#define T0   20
#define S0   24
#define CMID 12
#define T1   18
#define S1   22
#define COUT 36
#define T2   16
#define S2   20

#define H_TOTAL (B*CMID*T1*S1*S1*S1)

typedef unsigned long long u64;

__device__ float g_h[H_TOTAL];
__device__ float g_stats[24];
__device__ float g_scale[CMID];
__device__ float g_shift[CMID];

__device__ __forceinline__ void ffma2(u64& d, u64 a, u64 b, u64 c) {
    asm("fma.rn.f32x2 %0, %1, %2, %3;" : "=l"(d) : "l"(a), "l"(b), "l"(c));
}
__device__ __forceinline__ u64 pack2(float a, float b) {
    u64 r; asm("mov.b64 %0, {%1, %2};" : "=l"(r) : "f"(a), "f"(b)); return r;
}
__device__ __forceinline__ float lo32(u64 v){ return __uint_as_float((unsigned)v); }
__device__ __forceinline__ float hi32(u64 v){ return __uint_as_float((unsigned)(v>>32)); }

extern __shared__ float2 dynsm[];

// ---------------------------------------------------------------------------
__global__ void zero_stats_k() {
    if (threadIdx.x < 24) g_stats[threadIdx.x] = 0.0f;
}

// ---------------------------------------------------------------------------
// conv1 + ReLU + stats.  Block = (b,t,d) 22x22 plane, 12 channels.
// 8 warps: 2 channel-subgroups (6ch, warp-uniform) x 4 pixel-warps.
// Thread: 6ch x 2rows x 1pair.  121/128 pixel lanes active.
__global__ void __launch_bounds__(256, 2) conv1_k(const float* __restrict__ x,
                                                  const float* __restrict__ W1,
                                                  const float* __restrict__ b1) {
    float2* A  = dynsm;            // 9 subplanes x 24 rows x 12 f2 = 2592
    float2* Wm = A + 2592;         // 12j x 9s x 10 = 1080
    __shared__ float sred[24];

    const int d = blockIdx.x, t = blockIdx.y, b = blockIdx.z;
    const int tid  = threadIdx.x;
    const int warp = tid >> 5, lane = tid & 31;
    const int cw   = warp >> 2;               // 0..1 -> channels cw*6..+5
    const int pid  = ((warp & 3) << 5) | lane; // 0..127
    const bool act = pid < 121;
    const int ry = pid / 11;                  // 0..10 (rows 2ry,2ry+1)
    const int tx = pid - ry * 11;             // 0..10 (cols 2tx,2tx+1)

    u64 acc[6][2];
#pragma unroll
    for (int j = 0; j < 6; j++) { acc[j][0] = 0ull; acc[j][1] = 0ull; }
    if (tid < 24) sred[tid] = 0.0f;

    for (int ci = 0; ci < CIN; ci++) {
        __syncthreads();
        // stage 9 subplanes: 1296 float4 tasks
#pragma unroll
        for (int k = 0; k < 6; k++) {
            const int i = tid + k * 256;
            if (i < 1296) {
                const int s = i / 144, q = i - s * 144;
                const int kt = s / 3, kd = s - 3 * kt;
                const int base = ((b*CIN + ci)*T0 + (t+kt))*(S0*S0*S0)
                               + (d + kd)*(S0*S0) + 4*q;
                ((float4*)A)[s*144 + q] = *(const float4*)(x + base);
            }
        }
        // stage duplicated weights: 972 tasks
#pragma unroll
        for (int k = 0; k < 4; k++) {
            const int i = tid + k * 256;
            if (i < 972) {
                const int j = i / 81, r = i - 81*j;
                const int s = r / 9, tap = r - 9*s;
                const float w = W1[(j*CIN + ci)*81 + r];
                Wm[(j*9 + s)*10 + tap] = make_float2(w, w);
            }
        }
        __syncthreads();

        if (act) {
            for (int s = 0; s < 9; s++) {
                u64 pa0[4], pa1[4], pb[4];
#pragma unroll
                for (int kr = 0; kr < 4; kr++) {
                    const int ib = s*288 + (2*ry + kr)*12 + tx;
                    pa0[kr] = *(const u64*)&A[ib];
                    pa1[kr] = *(const u64*)&A[ib + 1];
                    pb[kr]  = pack2(hi32(pa0[kr]), lo32(pa1[kr]));
                }
#pragma unroll
                for (int jj = 0; jj < 6; jj++) {
                    const int j = cw*6 + jj;
                    const float2* wb = &Wm[(j*9 + s)*10];
                    const ulonglong2 w01 = *(const ulonglong2*)(wb + 0);
                    const ulonglong2 w23 = *(const ulonglong2*)(wb + 2);
                    const ulonglong2 w45 = *(const ulonglong2*)(wb + 4);
                    const ulonglong2 w67 = *(const ulonglong2*)(wb + 6);
                    const u64 w8 = *(const u64*)(wb + 8);
                    const u64 w[9] = {w01.x, w01.y, w23.x, w23.y,
                                      w45.x, w45.y, w67.x, w67.y, w8};
#pragma unroll
                    for (int kh = 0; kh < 3; kh++)
#pragma unroll
                        for (int r = 0; r < 2; r++) {
                            ffma2(acc[jj][r], w[3*kh+0], pa0[r+kh], acc[jj][r]);
                            ffma2(acc[jj][r], w[3*kh+1], pb[r+kh],  acc[jj][r]);
                            ffma2(acc[jj][r], w[3*kh+2], pa1[r+kh], acc[jj][r]);
                        }
                }
            }
        }
    }

    // epilogue: bias + relu + store + warp-reduced stats
#pragma unroll
    for (int jj = 0; jj < 6; jj++) {
        const int j = cw*6 + jj;
        float s_ = 0.0f, q_ = 0.0f;
        if (act) {
            const float bj = __ldg(&b1[j]);
#pragma unroll
            for (int r = 0; r < 2; r++) {
                const float v0 = fmaxf(lo32(acc[jj][r]) + bj, 0.0f);
                const float v1 = fmaxf(hi32(acc[jj][r]) + bj, 0.0f);
                const int hb = ((b*CMID + j)*T1 + t)*(S1*S1*S1)
                             + d*(S1*S1) + (2*ry + r)*S1 + 2*tx;
                *(float2*)&g_h[hb] = make_float2(v0, v1);
                s_ += v0 + v1;
                q_ += v0*v0 + v1*v1;
            }
        }
#pragma unroll
        for (int o = 16; o > 0; o >>= 1) {
            s_ += __shfl_down_sync(0xffffffffu, s_, o);
            q_ += __shfl_down_sync(0xffffffffu, q_, o);
        }
        if (lane == 0) {
            atomicAdd(&sred[j], s_);
            atomicAdd(&sred[12 + j], q_);
        }
    }
    __syncthreads();
    if (tid < 24) atomicAdd(&g_stats[tid], sred[tid]);
}

// ---------------------------------------------------------------------------
__global__ void finalize_k(const float* __restrict__ gamma,
                           const float* __restrict__ beta) {
    const int tid = threadIdx.x;
    if (tid < CMID) {
        const float N = (float)(B * T1 * S1 * S1 * S1);
        const float mean = g_stats[tid] / N;
        const float var  = g_stats[12 + tid] / N - mean * mean;
        const float inv  = rsqrtf(var + EPS);
        const float sc   = gamma[tid] * inv;
        g_scale[tid] = sc;
        g_shift[tid] = beta[tid] - mean * sc;
    }
}

// ---------------------------------------------------------------------------
// conv2 + ReLU, bn folded into staging.  Block = (b, t, 2 d-planes, 12-ch
// chunk).  12 warps: 3 channel-subgroups (4ch, warp-uniform) x 4 pixel-warps.
// Thread: 4ch x 4rows x 1pair.  100/128 pixel lanes active (2 planes x 50).
__global__ void __launch_bounds__(384, 1) conv2_k(const float* __restrict__ W2,
                                                  const float* __restrict__ b2,
                                                  float* __restrict__ out) {
    float2* A  = dynsm;            // 12 subplanes x 22 rows x 12 f2 = 3168
    float2* Wm = A + 3168;         // 12jl x 9s x 10 = 1080
    __shared__ float ssc[24];

    const int d0 = 2 * blockIdx.x;       // planes d0, d0+1
    const int t  = blockIdx.y;
    const int b  = blockIdx.z / 3;
    const int g  = blockIdx.z % 3;       // 12-channel chunk
    const int tid  = threadIdx.x;
    const int warp = tid >> 5, lane = tid & 31;
    const int cw   = warp >> 2;               // 0..2 -> local ch cw*4..+3
    const int pid  = ((warp & 3) << 5) | lane; // 0..127
    const bool act = pid < 100;
    const int p  = pid / 50;                  // plane select
    const int rm = pid - p * 50;
    const int ry = rm / 10;                   // rows 4ry..4ry+3
    const int tx = rm - ry * 10;              // cols 2tx,2tx+1

    if (tid < CMID) { ssc[tid] = g_scale[tid]; ssc[12 + tid] = g_shift[tid]; }

    u64 acc[4][4];
#pragma unroll
    for (int j = 0; j < 4; j++)
#pragma unroll
        for (int r = 0; r < 4; r++) acc[j][r] = 0ull;

    for (int ci = 0; ci < CMID; ci++) {
        __syncthreads();
        const float sc = ssc[ci], shv = ssc[12 + ci];
        // stage 12 subplanes (kt 0..2  x  dd 0..3): 2904 float2 tasks
#pragma unroll
        for (int k = 0; k < 8; k++) {
            const int i = tid + k * 384;
            if (i < 2904) {
                const int su = i / 242, rem = i - 242*su;
                const int rr = rem / 11, q = rem - 11*rr;
                const int kt = su >> 2, dd = su & 3;
                const int base = ((b*CMID + ci)*T1 + (t+kt))*(S1*S1*S1)
                               + (d0 + dd)*(S1*S1) + rr*S1 + 2*q;
                const float2 v = *(const float2*)(g_h + base);
                A[su*264 + rr*12 + q] =
                    make_float2(fmaf(v.x, sc, shv), fmaf(v.y, sc, shv));
            }
        }
        // stage duplicated weights: 972 tasks
#pragma unroll
        for (int k = 0; k < 3; k++) {
            const int i = tid + k * 384;
            if (i < 972) {
                const int jl = i / 81, r = i - 81*jl;
                const int s = r / 9, tap = r - 9*s;
                const float w = W2[((g*12 + jl)*CMID + ci)*81 + r];
                Wm[(jl*9 + s)*10 + tap] = make_float2(w, w);
            }
        }
        __syncthreads();

        if (act) {
            for (int s9 = 0; s9 < 9; s9++) {
                const int kt = s9 / 3, kd = s9 - 3*kt;
                const int su = (kt << 2) + p + kd;
                u64 pa0[6], pa1[6], pb[6];
#pragma unroll
                for (int kr = 0; kr < 6; kr++) {
                    const int ib = su*264 + (4*ry + kr)*12 + tx;
                    pa0[kr] = *(const u64*)&A[ib];
                    pa1[kr] = *(const u64*)&A[ib + 1];
                    pb[kr]  = pack2(hi32(pa0[kr]), lo32(pa1[kr]));
                }
#pragma unroll
                for (int jj = 0; jj < 4; jj++) {
                    const int jl = cw*4 + jj;
                    const float2* wb = &Wm[(jl*9 + s9)*10];
                    const ulonglong2 w01 = *(const ulonglong2*)(wb + 0);
                    const ulonglong2 w23 = *(const ulonglong2*)(wb + 2);
                    const ulonglong2 w45 = *(const ulonglong2*)(wb + 4);
                    const ulonglong2 w67 = *(const ulonglong2*)(wb + 6);
                    const u64 w8 = *(const u64*)(wb + 8);
                    const u64 w[9] = {w01.x, w01.y, w23.x, w23.y,
                                      w45.x, w45.y, w67.x, w67.y, w8};
#pragma unroll
                    for (int kh = 0; kh < 3; kh++)
#pragma unroll
                        for (int r = 0; r < 4; r++) {
                            ffma2(acc[jj][r], w[3*kh+0], pa0[r+kh], acc[jj][r]);
                            ffma2(acc[jj][r], w[3*kh+1], pb[r+kh],  acc[jj][r]);
                            ffma2(acc[jj][r], w[3*kh+2], pa1[r+kh], acc[jj][r]);
                        }
                }
            }
        }
    }

    if (act) {
#pragma unroll
        for (int jj = 0; jj < 4; jj++) {
            const int j = g*12 + cw*4 + jj;
            const float bo = __ldg(&b2[j]);
#pragma unroll
            for (int r = 0; r < 4; r++) {
                const int obase = ((b*COUT + j)*T2 + t)*(S2*S2*S2)
                                + (d0 + p)*(S2*S2) + (4*ry + r)*S2 + 2*tx;
                *(float2*)&out[obase] =
                    make_float2(fmaxf(lo32(acc[jj][r]) + bo, 0.0f),
                                fmaxf(hi32(acc[jj][r]) + bo, 0.0f));
            }
        }
    }
}

// ---------------------------------------------------------------------------
extern "C" void kernel_launch(void* const* d_in, const int* in_sizes, int n_in,
                              void* d_out, int out_size) {
    const float* x     = (const float*)d_in[0];
    const float* W1    = (const float*)d_in[1];
    const float* b1    = (const float*)d_in[2];
    const float* gamma = (const float*)d_in[3];
    const float* beta  = (const float*)d_in[4];
    const float* W2    = (const float*)d_in[5];
    const float* b2    = (const float*)d_in[6];
    float* out = (float*)d_out;

    const int smem1 = (2592 + 1080) * 8;   // 29376 B
    const int smem2 = (3168 + 1080) * 8;   // 33984 B
    cudaFuncSetAttribute(conv1_k, cudaFuncAttributeMaxDynamicSharedMemorySize, smem1);
    cudaFuncSetAttribute(conv2_k, cudaFuncAttributeMaxDynamicSharedMemorySize, smem2);

    zero_stats_k<<<1, 32>>>();
    conv1_k<<<dim3(S1, T1, B), 256, smem1>>>(x, W1, b1);
    finalize_k<<<1, 32>>>(gamma, beta);
    conv2_k<<<dim3(S2/2, T2, B * 3), 384, smem2>>>(W2, b2, out);
}

// round 8
// speedup vs baseline: 1.5961x; 1.5961x over previous
#include <cuda_runtime.h>
#include <cstdint>

#define EPS 1e-3f
#define Bn   8
#define CIN  4
#define T0   20
#define S0   24
#define CMID 12
#define T1   18
#define S1   22
#define COUT 36
#define T2   16
#define S2   20
#define HP   24              // padded w-stride of g_h (16B-aligned rows)

#define H_TOTAL (Bn*CMID*T1*S1*S1*HP)

typedef unsigned long long u64;

__device__ float g_h[H_TOTAL];
__device__ float g_stats[24];
__device__ float g_scale[CMID];
__device__ float g_shift[CMID];
__device__ float g_badj[COUT];

__device__ __forceinline__ void ffma2(u64& d, u64 a, u64 b, u64 c) {
    asm("fma.rn.f32x2 %0, %1, %2, %3;" : "=l"(d) : "l"(a), "l"(b), "l"(c));
}
__device__ __forceinline__ u64 pack2(float a, float b) {
    u64 r; asm("mov.b64 %0, {%1, %2};" : "=l"(r) : "f"(a), "f"(b)); return r;
}
__device__ __forceinline__ float lo32(u64 v){ return __uint_as_float((unsigned)v); }
__device__ __forceinline__ float hi32(u64 v){ return __uint_as_float((unsigned)(v>>32)); }

__device__ __forceinline__ void cpa16(uint32_t s, const void* g){
    asm volatile("cp.async.ca.shared.global [%0], [%1], 16;" :: "r"(s), "l"(g));
}
#define CP_COMMIT asm volatile("cp.async.commit_group;")
#define CP_WAIT0  asm volatile("cp.async.wait_group 0;" ::: "memory")

extern __shared__ char smemraw[];

// ---------------------------------------------------------------------------
__global__ void zero_stats_k() {
    if (threadIdx.x < 24) g_stats[threadIdx.x] = 0.0f;
}

// ---------------------------------------------------------------------------
// conv1 + ReLU + stats.  Block = (b,t,d) 22x22 plane.  384 thr: 3 ch-groups
// (4ch = 2 pairs) x 128 (121 active 2x2 tiles).  f32x2 packed over channels.
__global__ void __launch_bounds__(384, 2) conv1_k(const float* __restrict__ x,
                                                  const float* __restrict__ Wg1,
                                                  const float* __restrict__ b1) {
    float2* A0 = (float2*)smemraw;                 // 9 x 24 x 12 f2 = 2592
    float2* A1 = A0 + 2592;
    u64*    Wb0 = (u64*)(A1 + 2592);               // 6p x 9s x 3kh x 4 = 648
    u64*    Wb1 = Wb0 + 648;
    __shared__ float sred[24];

    const int d = blockIdx.x, t = blockIdx.y, b = blockIdx.z;
    const int tid = threadIdx.x;
    const int cg  = tid >> 7;              // 0..2 (warp-uniform)
    const int pid = tid & 127;
    const bool act = pid < 121;
    const int ry = pid / 11;               // rows 2ry,2ry+1
    const int tx = pid - ry * 11;          // cols 2tx,2tx+1

    const uint32_t sA0 = (uint32_t)__cvta_generic_to_shared(A0);
    const uint32_t sA1 = (uint32_t)__cvta_generic_to_shared(A1);

    if (tid < 24) sred[tid] = 0.0f;

    auto stageA = [&](uint32_t sbuf, int ci){
#pragma unroll
        for (int k = 0; k < 4; k++) {
            const int i = tid + k * 384;
            if (i < 1296) {
                const int su = i / 144, rem = i - 144*su;
                const int rr = rem / 6, q = rem - 6*rr;
                const int kt = su / 3, kd = su - 3*kt;
                const float* src = x + ((b*CIN + ci)*T0 + (t+kt))*(S0*S0*S0)
                                     + (d + kd)*(S0*S0) + rr*S0 + 4*q;
                cpa16(sbuf + (uint32_t)((su*288 + rr*12 + 2*q)*8), src);
            }
        }
    };
    auto stageW = [&](u64* wbuf, int ci){
#pragma unroll
        for (int k = 0; k < 2; k++) {
            const int i = tid + k * 384;
            if (i < 486) {
                const int p = i / 81, r = i - 81*p;
                const int s = r / 9, t9 = r - 9*s;
                const int kh = t9 / 3, kw = t9 - 3*kh;
                const float w0 = Wg1[(2*p*CIN + ci)*81 + r];
                const float w1 = Wg1[((2*p+1)*CIN + ci)*81 + r];
                wbuf[((p*9 + s)*3 + kh)*4 + kw] = pack2(w0, w1);
            }
        }
    };

    // prologue: stage ci=0 into buffer 0
    stageA(sA0, 0); CP_COMMIT;
    stageW(Wb0, 0);
    CP_WAIT0;
    __syncthreads();

    u64 acc[2][2][2];   // pair, row, col
#pragma unroll
    for (int p = 0; p < 2; p++)
#pragma unroll
        for (int r = 0; r < 2; r++) { acc[p][r][0] = 0ull; acc[p][r][1] = 0ull; }

    for (int ci = 0; ci < CIN; ci++) {
        const float2* Ac = (ci & 1) ? A1 : A0;
        const u64*    Wc = (ci & 1) ? Wb1 : Wb0;
        if (ci < CIN-1) {
            stageA((ci & 1) ? sA0 : sA1, ci+1); CP_COMMIT;
            stageW((ci & 1) ? Wb0 : Wb1, ci+1);
        }
        if (act) {
            for (int s9 = 0; s9 < 9; s9++) {
                u64 xx[4][4];
#pragma unroll
                for (int kr = 0; kr < 4; kr++) {
                    const float2* rp = &Ac[s9*288 + (2*ry + kr)*12 + tx];
                    const float2 f0 = rp[0], f1 = rp[1];
                    xx[kr][0] = pack2(f0.x, f0.x);
                    xx[kr][1] = pack2(f0.y, f0.y);
                    xx[kr][2] = pack2(f1.x, f1.x);
                    xx[kr][3] = pack2(f1.y, f1.y);
                }
#pragma unroll
                for (int kh = 0; kh < 3; kh++)
#pragma unroll
                    for (int p = 0; p < 2; p++) {
                        const u64* wb = Wc + ((cg*2 + p)*9 + s9)*12 + kh*4;
                        const ulonglong2 wab = *(const ulonglong2*)wb;
                        const u64 w2v = wb[2];
#pragma unroll
                        for (int r = 0; r < 2; r++)
#pragma unroll
                            for (int c = 0; c < 2; c++) {
                                ffma2(acc[p][r][c], wab.x, xx[r+kh][c+0], acc[p][r][c]);
                                ffma2(acc[p][r][c], wab.y, xx[r+kh][c+1], acc[p][r][c]);
                                ffma2(acc[p][r][c], w2v,   xx[r+kh][c+2], acc[p][r][c]);
                            }
                    }
            }
        }
        CP_WAIT0;
        __syncthreads();
    }

    // epilogue: bias + relu + store + stats
    float ss[2][2] = {{0,0},{0,0}}, qq[2][2] = {{0,0},{0,0}};
    if (act) {
#pragma unroll
        for (int p = 0; p < 2; p++) {
            const int j0 = 4*cg + 2*p;
            const float bj0 = __ldg(&b1[j0]), bj1 = __ldg(&b1[j0+1]);
#pragma unroll
            for (int r = 0; r < 2; r++) {
                const float v00 = fmaxf(lo32(acc[p][r][0]) + bj0, 0.0f);
                const float v01 = fmaxf(lo32(acc[p][r][1]) + bj0, 0.0f);
                const float v10 = fmaxf(hi32(acc[p][r][0]) + bj1, 0.0f);
                const float v11 = fmaxf(hi32(acc[p][r][1]) + bj1, 0.0f);
                const int hb = ((((b*CMID + j0)*T1 + t)*S1 + d)*S1 + (2*ry+r))*HP + 2*tx;
                *(float2*)&g_h[hb] = make_float2(v00, v01);
                *(float2*)&g_h[hb + T1*S1*S1*HP] = make_float2(v10, v11);
                ss[p][0] += v00 + v01;  qq[p][0] += v00*v00 + v01*v01;
                ss[p][1] += v10 + v11;  qq[p][1] += v10*v10 + v11*v11;
            }
        }
    }
    const int lane = tid & 31;
#pragma unroll
    for (int p = 0; p < 2; p++)
#pragma unroll
        for (int hlf = 0; hlf < 2; hlf++) {
            float s_ = ss[p][hlf], q_ = qq[p][hlf];
#pragma unroll
            for (int o = 16; o > 0; o >>= 1) {
                s_ += __shfl_down_sync(0xffffffffu, s_, o);
                q_ += __shfl_down_sync(0xffffffffu, q_, o);
            }
            if (lane == 0) {
                const int j = 4*cg + 2*p + hlf;
                atomicAdd(&sred[j], s_);
                atomicAdd(&sred[12 + j], q_);
            }
        }
    __syncthreads();
    if (tid < 24) atomicAdd(&g_stats[tid], sred[tid]);
}

// ---------------------------------------------------------------------------
__global__ void finalize_k(const float* __restrict__ gamma,
                           const float* __restrict__ beta) {
    const int tid = threadIdx.x;
    if (tid < CMID) {
        const float N = (float)(Bn * T1 * S1 * S1 * S1);
        const float mean = g_stats[tid] / N;
        const float var  = g_stats[12 + tid] / N - mean * mean;
        const float inv  = rsqrtf(var + EPS);
        const float sc   = gamma[tid] * inv;
        g_scale[tid] = sc;
        g_shift[tid] = beta[tid] - mean * sc;
    }
}

// bias adjust: b2'[j] = b2[j] + sum_ci shift[ci] * sum_taps W2[j,ci,:]
__global__ void badj_k(const float* __restrict__ W2,
                       const float* __restrict__ b2) {
    const int j = blockIdx.x;
    const int lane = threadIdx.x;
    float sum = 0.0f;
    for (int e = lane; e < CMID*81; e += 32) {
        const int ci = e / 81;
        sum += W2[j*CMID*81 + e] * g_shift[ci];
    }
#pragma unroll
    for (int o = 16; o > 0; o >>= 1) sum += __shfl_down_sync(0xffffffffu, sum, o);
    if (lane == 0) g_badj[j] = b2[j] + sum;
}

// ---------------------------------------------------------------------------
// conv2 + ReLU.  bn folded into weights (staged pre-scaled) + g_badj bias.
// Block = (b,t,d) 20x20 plane, all 36 ch.  480 thr: 9 ch-groups (4ch = 2
// pairs) x 50 tiles (2r x 4c).  cp.async double-buffered h staging.
__global__ void __launch_bounds__(480, 1) conv2_k(const float* __restrict__ Wg2,
                                                  float* __restrict__ out) {
    float2* A0 = (float2*)smemraw;                 // 9 x 22 x 12 f2 = 2376
    float2* A1 = A0 + 2376;
    u64*    Wb0 = (u64*)(A1 + 2376);               // 18p x 9s x 3kh x 4 = 1944
    u64*    Wb1 = Wb0 + 1944;

    const int d = blockIdx.x, t = blockIdx.y, b = blockIdx.z;
    const int tid = threadIdx.x;
    const bool act = tid < 450;
    const int cg  = tid / 50;              // 0..8
    const int pid = tid - cg * 50;
    const int ry = pid / 5;                // rows 2ry,2ry+1
    const int tx = pid - ry * 5;           // cols 4tx..4tx+3

    const uint32_t sA0 = (uint32_t)__cvta_generic_to_shared(A0);
    const uint32_t sA1 = (uint32_t)__cvta_generic_to_shared(A1);

    auto stageA = [&](uint32_t sbuf, int ci){
#pragma unroll
        for (int k = 0; k < 3; k++) {
            const int i = tid + k * 480;
            if (i < 1188) {
                const int su = i / 132, rem = i - 132*su;
                const int rr = rem / 6, q = rem - 6*rr;
                const int kt = su / 3, kd = su - 3*kt;
                const float* src = g_h + ((((b*CMID + ci)*T1 + (t+kt))*S1
                                   + (d + kd))*S1 + rr)*HP + 4*q;
                cpa16(sbuf + (uint32_t)((su*264 + rr*12 + 2*q)*8), src);
            }
        }
    };
    auto stageW = [&](u64* wbuf, int ci){
        const float sc = g_scale[ci];
#pragma unroll
        for (int k = 0; k < 4; k++) {
            const int i = tid + k * 480;
            if (i < 1458) {
                const int p = i / 81, r = i - 81*p;
                const int s = r / 9, t9 = r - 9*s;
                const int kh = t9 / 3, kw = t9 - 3*kh;
                const float w0 = Wg2[(2*p*CMID + ci)*81 + r] * sc;
                const float w1 = Wg2[((2*p+1)*CMID + ci)*81 + r] * sc;
                wbuf[((p*9 + s)*3 + kh)*4 + kw] = pack2(w0, w1);
            }
        }
    };

    stageA(sA0, 0); CP_COMMIT;
    stageW(Wb0, 0);
    CP_WAIT0;
    __syncthreads();

    u64 acc[2][2][4];   // pair, row, col
#pragma unroll
    for (int p = 0; p < 2; p++)
#pragma unroll
        for (int r = 0; r < 2; r++)
#pragma unroll
            for (int c = 0; c < 4; c++) acc[p][r][c] = 0ull;

    for (int ci = 0; ci < CMID; ci++) {
        const float2* Ac = (ci & 1) ? A1 : A0;
        const u64*    Wc = (ci & 1) ? Wb1 : Wb0;
        if (ci < CMID-1) {
            stageA((ci & 1) ? sA0 : sA1, ci+1); CP_COMMIT;
            stageW((ci & 1) ? Wb0 : Wb1, ci+1);
        }
        if (act) {
            for (int s9 = 0; s9 < 9; s9++) {
                u64 xx[4][6];
#pragma unroll
                for (int kr = 0; kr < 4; kr++) {
                    const float* rp = (const float*)&Ac[s9*264 + (2*ry + kr)*12 + 2*tx];
                    const float4 v4 = *(const float4*)rp;      // 16B aligned
                    const float2 v2 = *(const float2*)(rp + 4);
                    xx[kr][0] = pack2(v4.x, v4.x);
                    xx[kr][1] = pack2(v4.y, v4.y);
                    xx[kr][2] = pack2(v4.z, v4.z);
                    xx[kr][3] = pack2(v4.w, v4.w);
                    xx[kr][4] = pack2(v2.x, v2.x);
                    xx[kr][5] = pack2(v2.y, v2.y);
                }
#pragma unroll
                for (int kh = 0; kh < 3; kh++)
#pragma unroll
                    for (int p = 0; p < 2; p++) {
                        const u64* wb = Wc + ((cg*2 + p)*9 + s9)*12 + kh*4;
                        const ulonglong2 wab = *(const ulonglong2*)wb;
                        const u64 w2v = wb[2];
#pragma unroll
                        for (int r = 0; r < 2; r++)
#pragma unroll
                            for (int c = 0; c < 4; c++) {
                                ffma2(acc[p][r][c], wab.x, xx[r+kh][c+0], acc[p][r][c]);
                                ffma2(acc[p][r][c], wab.y, xx[r+kh][c+1], acc[p][r][c]);
                                ffma2(acc[p][r][c], w2v,   xx[r+kh][c+2], acc[p][r][c]);
                            }
                    }
            }
        }
        CP_WAIT0;
        __syncthreads();
    }

    if (act) {
#pragma unroll
        for (int p = 0; p < 2; p++) {
            const int j0 = 4*cg + 2*p;
            const float bj0 = __ldg(&g_badj[j0]), bj1 = __ldg(&g_badj[j0+1]);
#pragma unroll
            for (int r = 0; r < 2; r++) {
                const int ob = ((((b*COUT + j0)*T2 + t)*S2 + d)*S2 + (2*ry+r))*S2 + 4*tx;
                float4 olo, ohi;
                olo.x = fmaxf(lo32(acc[p][r][0]) + bj0, 0.0f);
                olo.y = fmaxf(lo32(acc[p][r][1]) + bj0, 0.0f);
                olo.z = fmaxf(lo32(acc[p][r][2]) + bj0, 0.0f);
                olo.w = fmaxf(lo32(acc[p][r][3]) + bj0, 0.0f);
                ohi.x = fmaxf(hi32(acc[p][r][0]) + bj1, 0.0f);
                ohi.y = fmaxf(hi32(acc[p][r][1]) + bj1, 0.0f);
                ohi.z = fmaxf(hi32(acc[p][r][2]) + bj1, 0.0f);
                ohi.w = fmaxf(hi32(acc[p][r][3]) + bj1, 0.0f);
                *(float4*)&out[ob] = olo;
                *(float4*)&out[ob + T2*S2*S2*S2] = ohi;
            }
        }
    }
}

// ---------------------------------------------------------------------------
extern "C" void kernel_launch(void* const* d_in, const int* in_sizes, int n_in,
                              void* d_out, int out_size) {
    const float* x     = (const float*)d_in[0];
    const float* W1    = (const float*)d_in[1];
    const float* b1    = (const float*)d_in[2];
    const float* gamma = (const float*)d_in[3];
    const float* beta  = (const float*)d_in[4];
    const float* W2    = (const float*)d_in[5];
    const float* b2    = (const float*)d_in[6];
    float* out = (float*)d_out;

    const int smem1 = (2592*2 + 648*2) * 8;    // 51840 B
    const int smem2 = (2376*2 + 1944*2) * 8;   // 69120 B
    cudaFuncSetAttribute(conv1_k, cudaFuncAttributeMaxDynamicSharedMemorySize, smem1);
    cudaFuncSetAttribute(conv2_k, cudaFuncAttributeMaxDynamicSharedMemorySize, smem2);

    zero_stats_k<<<1, 32>>>();
    conv1_k<<<dim3(S1, T1, Bn), 384, smem1>>>(x, W1, b1);
    finalize_k<<<1, 32>>>(gamma, beta);
    badj_k<<<COUT, 32>>>(W2, b2);
    conv2_k<<<dim3(S2, T2, Bn), 480, smem2>>>(W2, out);
}